// round 3
// baseline (speedup 1.0000x reference)
#include <cuda_runtime.h>
#include <math.h>

// Problem constants
#define BATCHV   4096
#define DIMV     100
#define TSTEPS   100     // T-1 integration steps
#define WIDTHV   200

// Kernel config
#define NTHREADS 256
#define M_TILE   32      // batch rows per CTA -> 128 CTAs
#define KC2      20      // k2 (k-pair) rows staged per cp.async stage
#define A_W      224     // activation buffer width (floats)
#define A0_W     104     // layer-0 input width (1+100 padded to 104, even)
#define WS_BUF   8000    // floats per weight stage buffer (KC2 * 400)

#define DW_STRIDE (DIMV * (TSTEPS + 1))   // 10100

typedef unsigned long long u64t;

// ---------------- packed f32x2 helpers ----------------
__device__ __forceinline__ u64t pack2(float lo, float hi) {
    u64t v; asm("mov.b64 %0, {%1, %2};" : "=l"(v) : "f"(lo), "f"(hi)); return v;
}
__device__ __forceinline__ float2 unpack2(u64t v) {
    float2 r; asm("mov.b64 {%0, %1}, %2;" : "=f"(r.x), "=f"(r.y) : "l"(v)); return r;
}
__device__ __forceinline__ u64t lds64(const float* p) {
    u64t v; unsigned a = (unsigned)__cvta_generic_to_shared(p);
    asm volatile("ld.shared.b64 %0, [%1];" : "=l"(v) : "r"(a));
    return v;
}
// d = a * b + d  (elementwise on packed f32 pairs) -> single FFMA2 SASS op
__device__ __forceinline__ void ffma2(u64t& d, u64t a, u64t b) {
    asm("fma.rn.f32x2 %0, %1, %2, %0;" : "+l"(d) : "l"(a), "l"(b));
}

// ---------------- cp.async helpers ----------------
__device__ __forceinline__ void cp_async16(void* sdst, const void* gsrc) {
    unsigned s = (unsigned)__cvta_generic_to_shared(sdst);
    asm volatile("cp.async.cg.shared.global [%0], [%1], 16;" :: "r"(s), "l"(gsrc));
}
__device__ __forceinline__ void cp_commit() { asm volatile("cp.async.commit_group;"); }
template<int N>
__device__ __forceinline__ void cp_wait() { asm volatile("cp.async.wait_group %0;" :: "n"(N)); }

// ---------------- pre-paired weight pool ----------------
// Layout per layer: [K2][N] of float2 = (W[2*k2][n], W[2*k2+1][n]), zero-padded odd K.
#define OFF_W0 0        // K2=51, N=200 -> 10200
#define OFF_W1 10200    // K2=100, N=200 -> 20000
#define OFF_W2 30200
#define OFF_W3 50200
#define OFF_WO 70200    // K2=100, N=100 -> 10000
__device__ float2 g_Wp[80200];

__global__ void pack_weights_kernel(const float* __restrict__ W, int K, int N, int off) {
    int idx = blockIdx.x * blockDim.x + threadIdx.x;
    int K2 = (K + 1) >> 1;
    if (idx >= K2 * N) return;
    int k2 = idx / N, n = idx - k2 * N;
    float lo = W[(2 * k2) * N + n];
    float hi = (2 * k2 + 1 < K) ? W[(2 * k2 + 1) * N + n] : 0.0f;
    g_Wp[off + idx] = make_float2(lo, hi);
}

// ---------------- per-layer GEMM (packed over k-parity) ----------------
// aOut[m, n] = act( aIn[m, 0:2*K2] @ W + b[n] )
// Thread (m_id, n_id) owns rows m_id*4..+3 and cols n_id + 32*j.
// acc[i][j] holds packed (even-k partial, odd-k partial); summed at the end.
template<int NJ, int NV, bool RELU>
__device__ __forceinline__ void gemm2(
    const float* __restrict__ aIn, int lda,
    float* __restrict__ aOut,
    const float2* __restrict__ gWp, const float* __restrict__ gB,
    int K2, float* __restrict__ ws,
    int m_id, int n_id, int tid)
{
    const int ROWF = 2 * NV;   // floats per k2 row in staged smem
    u64t acc[4][NJ];
    #pragma unroll
    for (int j = 0; j < NJ; ++j) {
        int n = n_id + 32 * j;
        float bv = (n < NV) ? gB[n] : 0.0f;
        u64t b2 = pack2(bv, 0.0f);
        #pragma unroll
        for (int i = 0; i < 4; ++i) acc[i][j] = b2;
    }

    const int nchunks = (K2 + KC2 - 1) / KC2;

    // prefetch chunk 0 into buffer 0
    {
        int kc0 = (KC2 < K2) ? KC2 : K2;
        int nf = kc0 * ROWF / 4;
        const float* gsrc = (const float*)gWp;
        for (int f = tid; f < nf; f += NTHREADS)
            cp_async16(ws + f * 4, gsrc + f * 4);
        cp_commit();
    }

    for (int ch = 0; ch < nchunks; ++ch) {
        int k20 = ch * KC2;
        int kc = K2 - k20; if (kc > KC2) kc = KC2;
        float* wbuf = ws + (ch & 1) * WS_BUF;

        if (ch + 1 < nchunks) {
            int k21 = k20 + KC2;
            int kc1 = K2 - k21; if (kc1 > KC2) kc1 = KC2;
            float* wn = ws + ((ch + 1) & 1) * WS_BUF;
            const float* gsrc = (const float*)(gWp + (size_t)k21 * NV);
            int nf = kc1 * ROWF / 4;
            for (int f = tid; f < nf; f += NTHREADS)
                cp_async16(wn + f * 4, gsrc + f * 4);
            cp_commit();
            cp_wait<1>();
        } else {
            cp_wait<0>();
        }
        __syncthreads();   // chunk visible; prev buffer free; prev layer stores visible

        const float* a0p = aIn + (m_id * 4 + 0) * lda + 2 * k20;
        const float* a1p = aIn + (m_id * 4 + 1) * lda + 2 * k20;
        const float* a2p = aIn + (m_id * 4 + 2) * lda + 2 * k20;
        const float* a3p = aIn + (m_id * 4 + 3) * lda + 2 * k20;
        const float* wp  = wbuf + 2 * n_id;

        #pragma unroll 4
        for (int k2 = 0; k2 < kc; ++k2) {
            u64t a0 = lds64(a0p + 2 * k2);
            u64t a1 = lds64(a1p + 2 * k2);
            u64t a2 = lds64(a2p + 2 * k2);
            u64t a3 = lds64(a3p + 2 * k2);
            #pragma unroll
            for (int j = 0; j < NJ; ++j) {
                u64t w = lds64(wp + k2 * ROWF + 64 * j);
                ffma2(acc[0][j], a0, w);
                ffma2(acc[1][j], a1, w);
                ffma2(acc[2][j], a2, w);
                ffma2(acc[3][j], a3, w);
            }
        }
        __syncthreads();   // done reading wbuf before refill
    }

    #pragma unroll
    for (int j = 0; j < NJ; ++j) {
        int n = n_id + 32 * j;
        #pragma unroll
        for (int i = 0; i < 4; ++i) {
            float2 v2 = unpack2(acc[i][j]);
            float v = v2.x + v2.y;
            if (RELU) v = fmaxf(v, 0.0f);
            if (n < NV) aOut[(m_id * 4 + i) * A_W + n] = v;
        }
    }
}

// ---------------- persistent trajectory kernel ----------------
// smem floats:
//   act0: 32*104 = 3328   [t | S | 0pad], S persists across steps
//   act1: 32*224 = 7168
//   act2: 32*224 = 7168
//   errs: 32*100 = 3200
//   ws:   2*8000 + 64 = 16064   (weight double buffer + tail-overread slack)
#define SMEM_FLOATS (M_TILE*A0_W + 2*M_TILE*A_W + M_TILE*DIMV + 2*WS_BUF + 64)
#define SMEM_BYTES  (SMEM_FLOATS * 4)

__global__ void __launch_bounds__(NTHREADS, 1)
control_solver_kernel(
    const float* __restrict__ S0,  const float* __restrict__ tg,
    const float* __restrict__ dW,
    const float* __restrict__ b0,  const float* __restrict__ b1,
    const float* __restrict__ b2,  const float* __restrict__ b3,
    const float* __restrict__ bout,
    float* __restrict__ out)
{
    extern __shared__ float sm[];
    float* act0 = sm;
    float* act1 = act0 + M_TILE * A0_W;
    float* act2 = act1 + M_TILE * A_W;
    float* errs = act2 + M_TILE * A_W;
    float* ws   = errs + M_TILE * DIMV;

    const int tid  = threadIdx.x;
    const int m_id = tid >> 5;
    const int n_id = tid & 31;
    const int gm0  = blockIdx.x * M_TILE;

    for (int idx = tid; idx < M_TILE * DIMV; idx += NTHREADS) {
        errs[idx] = 0.0f;
        int m = idx / DIMV, n = idx - (idx / DIMV) * DIMV;
        act0[m * A0_W + 1 + n] = S0[(size_t)(gm0 + m) * DIMV + n];
    }
    if (tid < M_TILE) {
        act0[tid * A0_W + 101] = 0.0f;   // zero-pad col for odd K of layer 0
        act0[tid * A0_W + 102] = 0.0f;
        act0[tid * A0_W + 103] = 0.0f;
    }
    const float h   = tg[1] - tg[0];
    const float sqh = sqrtf(h);
    __syncthreads();

    const float2* W0p = g_Wp + OFF_W0;
    const float2* W1p = g_Wp + OFF_W1;
    const float2* W2p = g_Wp + OFF_W2;
    const float2* W3p = g_Wp + OFF_W3;
    const float2* WOp = g_Wp + OFF_WO;

    for (int t = 0; t < TSTEPS; ++t) {
        if (tid < M_TILE) act0[tid * A0_W] = tg[t];
        __syncthreads();

        gemm2<7, WIDTHV, true >(act0, A0_W, act1, W0p, b0,   51,  ws, m_id, n_id, tid);
        gemm2<7, WIDTHV, true >(act1, A_W,  act2, W1p, b1,   100, ws, m_id, n_id, tid);
        gemm2<7, WIDTHV, true >(act2, A_W,  act1, W2p, b2,   100, ws, m_id, n_id, tid);
        gemm2<7, WIDTHV, true >(act1, A_W,  act2, W3p, b3,   100, ws, m_id, n_id, tid);
        gemm2<4, DIMV,   false>(act2, A_W,  act1, WOp, bout, 100, ws, m_id, n_id, tid);
        __syncthreads();   // u available in act1

        for (int idx = tid; idx < M_TILE * DIMV; idx += NTHREADS) {
            int m = idx / DIMV, n = idx - (idx / DIMV) * DIMV;
            float u = act1[m * A_W + n];
            errs[idx] = fmaf(u * u, h, errs[idx]);
            float dwi = sqh * dW[(size_t)(gm0 + m) * DW_STRIDE + t * DIMV + n];
            float S = act0[m * A0_W + 1 + n];
            act0[m * A0_W + 1 + n] = fmaf(u, h + dwi, S);
        }
        __syncthreads();
    }

    for (int idx = tid; idx < M_TILE * DIMV; idx += NTHREADS) {
        int m = idx / DIMV, n = idx - (idx / DIMV) * DIMV;
        float S = act0[m * A0_W + 1 + n];
        out[(size_t)(gm0 + m) * DIMV + n] = fmaf(S, S, errs[idx]);
    }
}

extern "C" void kernel_launch(void* const* d_in, const int* in_sizes, int n_in,
                              void* d_out, int out_size) {
    const float* S0   = (const float*)d_in[0];
    const float* tg   = (const float*)d_in[1];
    const float* dW   = (const float*)d_in[2];
    const float* W0   = (const float*)d_in[3];
    const float* b0   = (const float*)d_in[4];
    const float* W1   = (const float*)d_in[5];
    const float* b1   = (const float*)d_in[6];
    const float* W2   = (const float*)d_in[7];
    const float* b2   = (const float*)d_in[8];
    const float* W3   = (const float*)d_in[9];
    const float* b3   = (const float*)d_in[10];
    const float* Wout = (const float*)d_in[11];
    const float* bout = (const float*)d_in[12];
    float* out = (float*)d_out;

    // Pre-pair weights into (even-k, odd-k) float2 layout, zero-padded.
    pack_weights_kernel<<<(51  * 200 + 255) / 256, 256>>>(W0,   101, 200, OFF_W0);
    pack_weights_kernel<<<(100 * 200 + 255) / 256, 256>>>(W1,   200, 200, OFF_W1);
    pack_weights_kernel<<<(100 * 200 + 255) / 256, 256>>>(W2,   200, 200, OFF_W2);
    pack_weights_kernel<<<(100 * 200 + 255) / 256, 256>>>(W3,   200, 200, OFF_W3);
    pack_weights_kernel<<<(100 * 100 + 255) / 256, 256>>>(Wout, 200, 100, OFF_WO);

    cudaFuncSetAttribute(control_solver_kernel,
                         cudaFuncAttributeMaxDynamicSharedMemorySize, SMEM_BYTES);

    control_solver_kernel<<<BATCHV / M_TILE, NTHREADS, SMEM_BYTES>>>(
        S0, tg, dW, b0, b1, b2, b3, bout, out);
}

// round 4
// speedup vs baseline: 1.0188x; 1.0188x over previous
#include <cuda_runtime.h>
#include <math.h>

// Problem constants
#define BATCHV   4096
#define DIMV     100
#define TSTEPS   100
#define WIDTHV   200

// Config
#define NTHREADS 256
#define M_TILE   32            // 128 CTAs
#define A_W      224
#define A0_W     104
#define BUF_F    10400         // floats per weight stage buffer (26*400)
#define TOTCH    18            // chunks per step
#define DW_STRIDE (DIMV * (TSTEPS + 1))

typedef unsigned long long u64t;

// ---------------- packed f32x2 helpers ----------------
__device__ __forceinline__ u64t pack2(float lo, float hi) {
    u64t v; asm("mov.b64 %0, {%1, %2};" : "=l"(v) : "f"(lo), "f"(hi)); return v;
}
__device__ __forceinline__ float2 unpack2(u64t v) {
    float2 r; asm("mov.b64 {%0, %1}, %2;" : "=f"(r.x), "=f"(r.y) : "l"(v)); return r;
}
__device__ __forceinline__ void ffma2(u64t& d, u64t a, u64t b) {
    asm("fma.rn.f32x2 %0, %1, %2, %0;" : "+l"(d) : "l"(a), "l"(b));
}

// ---------------- cp.async helpers ----------------
__device__ __forceinline__ void cp_async16(void* sdst, const void* gsrc) {
    unsigned s = (unsigned)__cvta_generic_to_shared(sdst);
    asm volatile("cp.async.cg.shared.global [%0], [%1], 16;" :: "r"(s), "l"(gsrc));
}
__device__ __forceinline__ void cp_commit() { asm volatile("cp.async.commit_group;"); }
template<int N>
__device__ __forceinline__ void cp_wait() { asm volatile("cp.async.wait_group %0;" :: "n"(N)); }

// ---------------- pre-paired weight pool ----------------
// [K2][N] float2 = (W[2k2][n], W[2k2+1][n]), zero-padded odd K.
#define OFF_W0 0
#define OFF_W1 10200
#define OFF_W2 30200
#define OFF_W3 50200
#define OFF_WO 70200
__device__ __align__(16) float2 g_Wp[80200];

__global__ void pack_weights_kernel(const float* __restrict__ W, int K, int N, int off) {
    int idx = blockIdx.x * blockDim.x + threadIdx.x;
    int K2 = (K + 1) >> 1;
    if (idx >= K2 * N) return;
    int k2 = idx / N, n = idx - k2 * N;
    float lo = W[(2 * k2) * N + n];
    float hi = (2 * k2 + 1 < K) ? W[(2 * k2 + 1) * N + n] : 0.0f;
    g_Wp[off + idx] = make_float2(lo, hi);
}

// ---------------- continuous weight-chunk stream ----------------
// Per step: L0: chunks {k2 0..25, 26..50}; L1..L3, Lout: 4 chunks of 25 each.
__device__ __forceinline__ void prefetch_chunk(int c, float* buf, int tid) {
    int k20, kc, nv, off;
    if (c < 2) { off = OFF_W0; nv = 200; k20 = c ? 26 : 0; kc = c ? 25 : 26; }
    else {
        int r = c - 2; int L = r >> 2; int ci = r & 3;
        k20 = ci * 25; kc = 25;
        nv = (L == 3) ? 100 : 200;
        off = (L == 0) ? OFF_W1 : (L == 1) ? OFF_W2 : (L == 2) ? OFF_W3 : OFF_WO;
    }
    const float* src = (const float*)g_Wp + 2 * (off + k20 * nv);
    int nf = (kc * nv) >> 1;                 // 16B transfers
    for (int f = tid; f < nf; f += NTHREADS)
        cp_async16(buf + f * 4, src + f * 4);
    cp_commit();
}

// ---------------- per-layer GEMM, K-split across warp groups ----------------
// warp w: kg = w>>2 (K half), mg = w&3 (8 rows). Thread owns 8 rows x NJt cols.
// acc holds packed (even-k, odd-k) partials; kg halves combined via scratch.
template<int NJt, int NVt, int K2t, int NCH, bool RELU, int LDA>
__device__ __forceinline__ void gemm(
    const float* __restrict__ aIn, float* __restrict__ aOut,
    float* __restrict__ scratch, const float* __restrict__ sb,
    float* __restrict__ ws, int& cur,
    int kg, int mg, int n_id, int tid)
{
    u64t acc[8][NJt];
    #pragma unroll
    for (int j = 0; j < NJt; ++j) {
        int n = n_id + 32 * j;
        float bv = (!kg && n < NVt) ? sb[n] : 0.0f;
        u64t b2 = pack2(bv, 0.0f);
        #pragma unroll
        for (int i = 0; i < 8; ++i) acc[i][j] = b2;
    }

    int k2base = 0;
    for (int ch = 0; ch < NCH; ++ch) {
        const int kc = (K2t == 51) ? (ch == 0 ? 26 : 25) : 25;
        cp_wait<1>();
        __syncthreads();                       // chunk `cur` visible; buffer (cur+2)%3 free
        int cn = cur + 2;
        prefetch_chunk(cn % TOTCH, ws + (cn % 3) * BUF_F, tid);
        const float* wbuf = ws + (cur % 3) * BUF_F;

        const int c0  = (kc + 1) >> 1;
        const int s   = kg ? c0 : 0;
        const int cnt = kg ? (kc - c0) : c0;
        const u64t* abase = (const u64t*)(aIn + mg * 8 * LDA) + (k2base + s);
        const u64t* wp    = (const u64t*)wbuf + (size_t)s * NVt + n_id;

        #pragma unroll 4
        for (int k2 = 0; k2 < cnt; ++k2) {
            u64t a[8];
            #pragma unroll
            for (int i = 0; i < 8; ++i) a[i] = abase[i * (LDA / 2) + k2];
            #pragma unroll
            for (int j = 0; j < NJt; ++j) {
                u64t w = wp[k2 * NVt + 32 * j];   // pad-col overreads land in unread pad cols
                #pragma unroll
                for (int i = 0; i < 8; ++i) ffma2(acc[i][j], a[i], w);
            }
        }
        k2base += kc;
        cur++;
    }

    __syncthreads();                            // all partials done; aIn (=scratch) dead
    if (kg) {
        #pragma unroll
        for (int j = 0; j < NJt; ++j) {
            int n = n_id + 32 * j;
            #pragma unroll
            for (int i = 0; i < 8; ++i) {
                float2 v = unpack2(acc[i][j]);
                scratch[(mg * 8 + i) * A_W + n] = v.x + v.y;
            }
        }
    }
    __syncthreads();
    if (!kg) {
        #pragma unroll
        for (int j = 0; j < NJt; ++j) {
            int n = n_id + 32 * j;
            #pragma unroll
            for (int i = 0; i < 8; ++i) {
                float2 v = unpack2(acc[i][j]);
                float r = v.x + v.y + scratch[(mg * 8 + i) * A_W + n];
                if (RELU) r = fmaxf(r, 0.0f);
                aOut[(mg * 8 + i) * A_W + n] = r;
            }
        }
    }
    // aOut visibility to next layer is covered by next gemm's top __syncthreads.
}

// ---------------- persistent trajectory kernel ----------------
// smem: ws 3*10400 | act0 32*104 | act1 32*224 | act2 32*224 | errs 3200 | sb 1024
#define SMEM_FLOATS (3*BUF_F + M_TILE*A0_W + 2*M_TILE*A_W + M_TILE*DIMV + 1024)
#define SMEM_BYTES  (SMEM_FLOATS * 4)

__global__ void __launch_bounds__(NTHREADS, 1)
control_solver_kernel(
    const float* __restrict__ S0,  const float* __restrict__ tg,
    const float* __restrict__ dW,
    const float* __restrict__ b0,  const float* __restrict__ b1,
    const float* __restrict__ b2,  const float* __restrict__ b3,
    const float* __restrict__ bout,
    float* __restrict__ out)
{
    extern __shared__ float sm[];
    float* ws   = sm;
    float* act0 = ws + 3 * BUF_F;
    float* act1 = act0 + M_TILE * A0_W;
    float* act2 = act1 + M_TILE * A_W;
    float* errs = act2 + M_TILE * A_W;
    float* sb   = errs + M_TILE * DIMV;     // biases [0..899], timegrid [904..1004]
    float* tgs  = sb + 904;

    const int tid  = threadIdx.x;
    const int w    = tid >> 5;
    const int kg   = w >> 2;
    const int mg   = w & 3;
    const int n_id = tid & 31;
    const int gm0  = blockIdx.x * M_TILE;

    // prime the chunk stream immediately (overlaps with init below)
    prefetch_chunk(0, ws, tid);
    prefetch_chunk(1, ws + BUF_F, tid);

    for (int i = tid; i < 200; i += NTHREADS) {
        sb[i]       = b0[i];
        sb[200 + i] = b1[i];
        sb[400 + i] = b2[i];
        sb[600 + i] = b3[i];
        if (i < 100) sb[800 + i] = bout[i];
    }
    for (int i = tid; i <= TSTEPS; i += NTHREADS) tgs[i] = tg[i];
    for (int idx = tid; idx < M_TILE * DIMV; idx += NTHREADS) {
        errs[idx] = 0.0f;
        int m = idx / DIMV, n = idx - (idx / DIMV) * DIMV;
        act0[m * A0_W + 1 + n] = S0[(size_t)(gm0 + m) * DIMV + n];
    }
    if (tid < M_TILE) {
        act0[tid * A0_W + 101] = 0.0f;
        act0[tid * A0_W + 102] = 0.0f;
        act0[tid * A0_W + 103] = 0.0f;
    }
    __syncthreads();
    const float h   = tgs[1] - tgs[0];
    const float sqh = sqrtf(h);

    int cur = 0;
    for (int t = 0; t < TSTEPS; ++t) {
        if (tid < M_TILE) act0[tid * A0_W] = tgs[t];

        gemm<7, 200, 51, 2, true, A0_W>(act0, act1, act2, sb, ws, cur, kg, mg, n_id, tid);

        {   // hidden layers 1..3, ping-pong act1/act2, scratch = dead input
            const float* in = act1; float* op = act2;
            for (int L = 1; L <= 3; ++L) {
                gemm<7, 200, 100, 4, true, A_W>(in, op, (float*)in, sb + 200 * L,
                                                ws, cur, kg, mg, n_id, tid);
                const float* tmp = in; in = op; op = (float*)tmp;
            }
        }
        // after 3 hidden layers: h3 in act2
        gemm<4, 100, 100, 4, false, A_W>(act2, act1, act2, sb + 800,
                                         ws, cur, kg, mg, n_id, tid);
        __syncthreads();   // u in act1 visible

        for (int idx = tid; idx < M_TILE * DIMV; idx += NTHREADS) {
            int m = idx / DIMV, n = idx - (idx / DIMV) * DIMV;
            float u = act1[m * A_W + n];
            errs[idx] = fmaf(u * u, h, errs[idx]);
            float dwi = sqh * dW[(size_t)(gm0 + m) * DW_STRIDE + t * DIMV + n];
            float S = act0[m * A0_W + 1 + n];
            act0[m * A0_W + 1 + n] = fmaf(u, h + dwi, S);
        }
        __syncthreads();
    }

    for (int idx = tid; idx < M_TILE * DIMV; idx += NTHREADS) {
        int m = idx / DIMV, n = idx - (idx / DIMV) * DIMV;
        float S = act0[m * A0_W + 1 + n];
        out[(size_t)(gm0 + m) * DIMV + n] = fmaf(S, S, errs[idx]);
    }
    cp_wait<0>();   // drain tail prefetches
}

extern "C" void kernel_launch(void* const* d_in, const int* in_sizes, int n_in,
                              void* d_out, int out_size) {
    const float* S0   = (const float*)d_in[0];
    const float* tg   = (const float*)d_in[1];
    const float* dW   = (const float*)d_in[2];
    const float* W0   = (const float*)d_in[3];
    const float* b0   = (const float*)d_in[4];
    const float* W1   = (const float*)d_in[5];
    const float* b1   = (const float*)d_in[6];
    const float* W2   = (const float*)d_in[7];
    const float* b2   = (const float*)d_in[8];
    const float* W3   = (const float*)d_in[9];
    const float* b3   = (const float*)d_in[10];
    const float* Wout = (const float*)d_in[11];
    const float* bout = (const float*)d_in[12];
    float* out = (float*)d_out;

    pack_weights_kernel<<<(51  * 200 + 255) / 256, 256>>>(W0,   101, 200, OFF_W0);
    pack_weights_kernel<<<(100 * 200 + 255) / 256, 256>>>(W1,   200, 200, OFF_W1);
    pack_weights_kernel<<<(100 * 200 + 255) / 256, 256>>>(W2,   200, 200, OFF_W2);
    pack_weights_kernel<<<(100 * 200 + 255) / 256, 256>>>(W3,   200, 200, OFF_W3);
    pack_weights_kernel<<<(100 * 100 + 255) / 256, 256>>>(Wout, 200, 100, OFF_WO);

    cudaFuncSetAttribute(control_solver_kernel,
                         cudaFuncAttributeMaxDynamicSharedMemorySize, SMEM_BYTES);

    control_solver_kernel<<<BATCHV / M_TILE, NTHREADS, SMEM_BYTES>>>(
        S0, tg, dW, b0, b1, b2, b3, bout, out);
}